// round 3
// baseline (speedup 1.0000x reference)
#include <cuda_runtime.h>
#include <math.h>

// Problem constants
#define BB 64
#define NN 197
#define CC 1024
#define HH 16
#define DD 64
#define MTOT (BB*NN)          // 12608
#define SEQ 196               // roped positions

// Scratch (static device globals — no runtime allocation)
__device__ __align__(16) float g_qkv[(size_t)MTOT * 3 * CC];   // (B*N, 3C)
__device__ __align__(16) float g_att[(size_t)MTOT * CC];       // (B*N, C)

// ---------------------------------------------------------------------------
// RoPE in-place on Q and K slices of g_qkv, tokens n=1..196.
// freq base[pr] = 10000^(-2*pr/64), angle = t * base (same for both elements
// of an interleaved pair, since the table is tiled f=[f,f] and pair (2i,2i+1)
// reads table entries 2i and 2i+1 which both equal base[i']... careful:
// reference table: f = concat([f_half, f_half]) so table[d] = t*base[d mod 32].
// For pair (2i, 2i+1): table[2i] = t*base[(2i)%32], table[2i+1]=t*base[(2i+1)%32].
// These differ! So compute both angles.
// out[2i]   = x[2i]*cos(a0) - x[2i+1]*sin(a0),  a0 = t*base[(2i)&31]
// out[2i+1] = x[2i+1]*cos(a1) + x[2i]*sin(a1),  a1 = t*base[(2i+1)&31]
// ---------------------------------------------------------------------------
__global__ void rope_kernel() {
    const int PAIRS = BB * HH * SEQ * (DD / 2);   // per tensor
    int idx = blockIdx.x * blockDim.x + threadIdx.x;
    if (idx >= 2 * PAIRS) return;
    int which = (idx < PAIRS) ? 0 : 1;            // 0 = q, 1 = k
    int p = which ? (idx - PAIRS) : idx;
    int pr = p & 31;                              // pair index (0..31)
    int rest = p >> 5;                            // B*H*SEQ
    int t = rest % SEQ;
    int bh = rest / SEQ;
    int b = bh >> 4, h = bh & 15;
    int n = t + 1;
    size_t off = (size_t)(b * NN + n) * (3 * CC) + which * CC + h * DD + 2 * pr;

    // d0 = 2*pr, d1 = 2*pr+1; base[d&31]
    float base0 = powf(10000.0f, -(float)(2 * ((2 * pr) & 31)) / 64.0f);
    float base1 = powf(10000.0f, -(float)(2 * ((2 * pr + 1) & 31)) / 64.0f);
    float a0 = (float)t * base0;
    float a1 = (float)t * base1;
    float c0, s0, c1, s1;
    sincosf(a0, &s0, &c0);
    sincosf(a1, &s1, &c1);

    float x0 = g_qkv[off], x1 = g_qkv[off + 1];
    g_qkv[off]     = x0 * c0 - x1 * s0;
    g_qkv[off + 1] = x1 * c1 + x0 * s1;
}

// ---------------------------------------------------------------------------
// SGEMM NT: C[m][n] = sum_k A[m][k]*B[n][k] + bias[n]
// A: (M,K) row-major, B: (N,K) row-major. 128x128x8 tile, 8x8 per thread.
// ---------------------------------------------------------------------------
#define BM 128
#define BN 128
#define BK 8
__global__ __launch_bounds__(256) void sgemm_nt(
    const float* __restrict__ A, const float* __restrict__ Bw,
    const float* __restrict__ bias, float* __restrict__ C,
    int M, int N, int K)
{
    __shared__ float As[BK][BM + 4];
    __shared__ float Bs[BK][BN + 4];
    const int tid = threadIdx.x;
    const int bm = blockIdx.y * BM;
    const int bn = blockIdx.x * BN;
    const int lrow = tid >> 1;            // 0..127
    const int lcol = (tid & 1) << 2;      // 0 or 4
    const int tr = (tid >> 4) << 3;       // thread row*8
    const int tc = (tid & 15) << 3;       // thread col*8

    float acc[8][8];
#pragma unroll
    for (int i = 0; i < 8; i++)
#pragma unroll
        for (int j = 0; j < 8; j++) acc[i][j] = 0.0f;

    const bool arow_ok = (bm + lrow) < M;
    const float* Aptr = A + (size_t)(bm + lrow) * K + lcol;
    const float* Bptr = Bw + (size_t)(bn + lrow) * K + lcol;

    for (int k0 = 0; k0 < K; k0 += BK) {
        float4 av = arow_ok ? *(const float4*)(Aptr + k0) : make_float4(0.f, 0.f, 0.f, 0.f);
        float4 bv = *(const float4*)(Bptr + k0);
        As[lcol + 0][lrow] = av.x; As[lcol + 1][lrow] = av.y;
        As[lcol + 2][lrow] = av.z; As[lcol + 3][lrow] = av.w;
        Bs[lcol + 0][lrow] = bv.x; Bs[lcol + 1][lrow] = bv.y;
        Bs[lcol + 2][lrow] = bv.z; Bs[lcol + 3][lrow] = bv.w;
        __syncthreads();
#pragma unroll
        for (int kk = 0; kk < BK; kk++) {
            float4 a0 = *(const float4*)&As[kk][tr];
            float4 a1 = *(const float4*)&As[kk][tr + 4];
            float4 b0 = *(const float4*)&Bs[kk][tc];
            float4 b1 = *(const float4*)&Bs[kk][tc + 4];
            float ra[8] = {a0.x, a0.y, a0.z, a0.w, a1.x, a1.y, a1.z, a1.w};
            float rb[8] = {b0.x, b0.y, b0.z, b0.w, b1.x, b1.y, b1.z, b1.w};
#pragma unroll
            for (int i = 0; i < 8; i++)
#pragma unroll
                for (int j = 0; j < 8; j++)
                    acc[i][j] = fmaf(ra[i], rb[j], acc[i][j]);
        }
        __syncthreads();
    }

    float bb[8];
#pragma unroll
    for (int j = 0; j < 8; j++) bb[j] = bias[bn + tc + j];
#pragma unroll
    for (int i = 0; i < 8; i++) {
        int gm = bm + tr + i;
        if (gm < M) {
            float* crow = C + (size_t)gm * N + bn + tc;
#pragma unroll
            for (int j = 0; j < 8; j++) crow[j] = acc[i][j] + bb[j];
        }
    }
}

// ---------------------------------------------------------------------------
// Attention: one block per (b,h). K/V staged in smem, one thread per query
// row, online softmax, fp32 accumulation.
// ---------------------------------------------------------------------------
#define ATTN_THREADS 224
#define ATTN_SMEM (2 * NN * DD * (int)sizeof(float))   // 100864 B

__global__ __launch_bounds__(ATTN_THREADS) void attn_kernel()
{
    extern __shared__ float sm[];
    float* Ks = sm;
    float* Vs = sm + NN * DD;
    const int bh = blockIdx.x;
    const int b = bh >> 4, h = bh & 15;
    const int tid = threadIdx.x;
    const size_t rowbase = (size_t)b * NN * (3 * CC) + (size_t)h * DD;

    // cooperative load of K and V tiles (197x64 each)
    for (int i = tid; i < NN * (DD / 4); i += ATTN_THREADS) {
        int j = i >> 4;
        int d4 = (i & 15) << 2;
        size_t g = rowbase + (size_t)j * (3 * CC) + d4;
        *(float4*)(Ks + j * DD + d4) = *(const float4*)(g_qkv + g + CC);
        *(float4*)(Vs + j * DD + d4) = *(const float4*)(g_qkv + g + 2 * CC);
    }
    __syncthreads();
    if (tid >= NN) return;

    float q[DD];
    {
        const float4* qp = (const float4*)(g_qkv + rowbase + (size_t)tid * (3 * CC));
#pragma unroll
        for (int i = 0; i < 16; i++) {
            float4 v = qp[i];
            q[4 * i] = v.x; q[4 * i + 1] = v.y; q[4 * i + 2] = v.z; q[4 * i + 3] = v.w;
        }
    }

    float mx = -3.4e38f, l = 0.0f;
    float acc[DD];
#pragma unroll
    for (int d = 0; d < DD; d++) acc[d] = 0.0f;
    const float scale = 0.125f;   // 64^-0.5

    for (int j = 0; j < NN; j++) {
        const float4* kr = (const float4*)(Ks + j * DD);
        float s = 0.0f;
#pragma unroll
        for (int i = 0; i < 16; i++) {
            float4 kv = kr[i];
            s = fmaf(q[4 * i], kv.x, s);
            s = fmaf(q[4 * i + 1], kv.y, s);
            s = fmaf(q[4 * i + 2], kv.z, s);
            s = fmaf(q[4 * i + 3], kv.w, s);
        }
        s *= scale;
        if (s > mx) {
            float corr = __expf(mx - s);
            l *= corr;
#pragma unroll
            for (int d = 0; d < DD; d++) acc[d] *= corr;
            mx = s;
        }
        float p = __expf(s - mx);
        l += p;
        const float4* vr = (const float4*)(Vs + j * DD);
#pragma unroll
        for (int i = 0; i < 16; i++) {
            float4 vv = vr[i];
            acc[4 * i]     = fmaf(p, vv.x, acc[4 * i]);
            acc[4 * i + 1] = fmaf(p, vv.y, acc[4 * i + 1]);
            acc[4 * i + 2] = fmaf(p, vv.z, acc[4 * i + 2]);
            acc[4 * i + 3] = fmaf(p, vv.w, acc[4 * i + 3]);
        }
    }

    float inv = 1.0f / l;
    float* op = g_att + (size_t)(b * NN + tid) * CC + h * DD;
#pragma unroll
    for (int i = 0; i < 16; i++) {
        float4 o;
        o.x = acc[4 * i] * inv;
        o.y = acc[4 * i + 1] * inv;
        o.z = acc[4 * i + 2] * inv;
        o.w = acc[4 * i + 3] * inv;
        *(float4*)(op + 4 * i) = o;
    }
}

// ---------------------------------------------------------------------------
// Launch
// ---------------------------------------------------------------------------
extern "C" void kernel_launch(void* const* d_in, const int* in_sizes, int n_in,
                              void* d_out, int out_size)
{
    const float* x      = (const float*)d_in[0];
    const float* qkv_w  = (const float*)d_in[1];
    const float* qkv_b  = (const float*)d_in[2];
    const float* proj_w = (const float*)d_in[3];
    const float* proj_b = (const float*)d_in[4];
    float* out = (float*)d_out;

    float* qkv = nullptr;
    float* att = nullptr;
    cudaGetSymbolAddress((void**)&qkv, g_qkv);
    cudaGetSymbolAddress((void**)&att, g_att);

    cudaFuncSetAttribute(attn_kernel, cudaFuncAttributeMaxDynamicSharedMemorySize, ATTN_SMEM);

    // 1) QKV GEMM: (12608 x 1024) @ (3072 x 1024)^T + bias -> g_qkv
    {
        dim3 grid(3 * CC / BN, (MTOT + BM - 1) / BM);
        sgemm_nt<<<grid, 256>>>(x, qkv_w, qkv_b, qkv, MTOT, 3 * CC, CC);
    }

    // 2) RoPE on Q,K (in place)
    {
        const int PAIRS = BB * HH * SEQ * (DD / 2);
        rope_kernel<<<(2 * PAIRS + 255) / 256, 256>>>();
    }

    // 3) Attention
    attn_kernel<<<BB * HH, ATTN_THREADS, ATTN_SMEM>>>();

    // 4) Output projection: (12608 x 1024) @ (1024 x 1024)^T + bias -> out
    {
        dim3 grid(CC / BN, (MTOT + BM - 1) / BM);
        sgemm_nt<<<grid, 256>>>(att, proj_w, proj_b, out, MTOT, CC, CC);
    }
}

// round 5
// speedup vs baseline: 1.9562x; 1.9562x over previous
#include <cuda_runtime.h>
#include <cuda_bf16.h>
#include <math.h>
#include <stdint.h>

// Problem constants
#define BB 64
#define NN 197
#define CC 1024
#define HH 16
#define DD 64
#define MTOT (BB*NN)          // 12608
#define MPAD 12672            // 99 * 128
#define SEQ 196
#define K3 3072               // 3x split-K
#define KCH32 (K3/32)         // 96 mainloop iters

// ---------------------------------------------------------------------------
// Scratch (static device globals)
// ---------------------------------------------------------------------------
__device__ __align__(16) float g_qkv[(size_t)MTOT * 3 * CC];     // (12608, 3072)
__device__ __align__(16) float g_att[(size_t)MTOT * CC];         // (12608, 1024)
__device__ __align__(16) __nv_bfloat16 g_A1[(size_t)MPAD * K3];  // x split
__device__ __align__(16) __nv_bfloat16 g_A2[(size_t)MPAD * K3];  // att split
__device__ __align__(16) __nv_bfloat16 g_Bq[(size_t)(3 * CC) * K3];
__device__ __align__(16) __nv_bfloat16 g_Bp[(size_t)CC * K3];

// ---------------------------------------------------------------------------
// PTX helpers (base sm_100-legal only: ldmatrix / mma.sync / cp.async)
// ---------------------------------------------------------------------------
__device__ __forceinline__ uint32_t smem_to_u32(const void* p) {
    uint32_t a;
    asm("{ .reg .u64 t; cvta.to.shared.u64 t, %1; cvt.u32.u64 %0, t; }" : "=r"(a) : "l"(p));
    return a;
}

#define CP_ASYNC16(dst, src) \
    asm volatile("cp.async.cg.shared.global [%0], [%1], 16;" :: "r"(dst), "l"(src) : "memory")
#define CP_COMMIT() asm volatile("cp.async.commit_group;" ::: "memory")
#define CP_WAIT1()  asm volatile("cp.async.wait_group 1;" ::: "memory")
#define CP_WAIT0()  asm volatile("cp.async.wait_group 0;" ::: "memory")

#define LDSM_X4(r0, r1, r2, r3, addr) \
    asm volatile("ldmatrix.sync.aligned.m8n8.x4.shared.b16 {%0,%1,%2,%3}, [%4];" \
        : "=r"(r0), "=r"(r1), "=r"(r2), "=r"(r3) : "r"(addr))

#define MMA16816(c, a, b) \
    asm volatile("mma.sync.aligned.m16n8k16.row.col.f32.bf16.bf16.f32 " \
        "{%0,%1,%2,%3}, {%4,%5,%6,%7}, {%8,%9}, {%0,%1,%2,%3};" \
        : "+f"((c)[0]), "+f"((c)[1]), "+f"((c)[2]), "+f"((c)[3]) \
        : "r"((a)[0]), "r"((a)[1]), "r"((a)[2]), "r"((a)[3]), "r"((b)[0]), "r"((b)[1]))

// 16B-chunk XOR swizzle for 64B rows: chunk' = chunk ^ ((row>>1)&3)
// -> the 8 rows of any ldmatrix 8x8 tile land in 8 distinct 16B bank granules.
__device__ __forceinline__ uint32_t swz(int row, int chunk) {
    return (uint32_t)(row * 64 + ((chunk ^ ((row >> 1) & 3)) << 4));
}

// ---------------------------------------------------------------------------
// Split fp32 -> bf16 hi/lo, expanded along K into 3 blocks of 1024.
// is_a=1: [hi | hi | lo]   is_a=0: [hi | lo | hi]
// ---------------------------------------------------------------------------
__global__ void split_bf16_kernel(const float* __restrict__ in,
                                  __nv_bfloat16* __restrict__ out,
                                  int rows, int is_a) {
    int idx = blockIdx.x * blockDim.x + threadIdx.x;
    int total = rows * 256;
    if (idx >= total) return;
    int r = idx >> 8;
    int c4 = (idx & 255) << 2;
    float4 v = *(const float4*)(in + (size_t)r * 1024 + c4);
    float f[4] = {v.x, v.y, v.z, v.w};
    uint32_t hp[2], lp[2];
#pragma unroll
    for (int i = 0; i < 2; i++) {
        __nv_bfloat16 h0 = __float2bfloat16_rn(f[2 * i]);
        __nv_bfloat16 h1 = __float2bfloat16_rn(f[2 * i + 1]);
        __nv_bfloat16 l0 = __float2bfloat16_rn(f[2 * i]     - __bfloat162float(h0));
        __nv_bfloat16 l1 = __float2bfloat16_rn(f[2 * i + 1] - __bfloat162float(h1));
        hp[i] = (uint32_t)__bfloat16_as_ushort(h0) | ((uint32_t)__bfloat16_as_ushort(h1) << 16);
        lp[i] = (uint32_t)__bfloat16_as_ushort(l0) | ((uint32_t)__bfloat16_as_ushort(l1) << 16);
    }
    uint2 hv = make_uint2(hp[0], hp[1]);
    uint2 lv = make_uint2(lp[0], lp[1]);
    size_t base = (size_t)r * K3 + c4;
    *(uint2*)(out + base) = hv;
    *(uint2*)(out + base + 1024) = is_a ? hv : lv;
    *(uint2*)(out + base + 2048) = is_a ? lv : hv;
}

// ---------------------------------------------------------------------------
// bf16 tensor-core GEMM (mma.sync): C(m,n) = sum_k A'(m,k) B'(n,k) + bias(n)
// 128x128x32 block tile, 8 warps (2x4), 64x32 warp tile, m16n8k16 atoms,
// cp.async double-buffered smem, swizzled ldmatrix.
// ---------------------------------------------------------------------------
__device__ __forceinline__ void gemm_issue_loads(
    const __nv_bfloat16* Ab, const __nv_bfloat16* Bb,
    uint32_t sA, uint32_t sB, int tid, int kc)
{
#pragma unroll
    for (int i = 0; i < 2; i++) {
        int idx = tid + (i << 8);          // 0..511
        int row = idx >> 2;                // 0..127
        int u = idx & 3;                   // 16B chunk in 64B row
        uint32_t off = swz(row, u);
        CP_ASYNC16(sA + off, (const char*)(Ab + (size_t)row * K3 + kc * 32) + u * 16);
        CP_ASYNC16(sB + off, (const char*)(Bb + (size_t)row * K3 + kc * 32) + u * 16);
    }
}

__global__ __launch_bounds__(256) void gemm_tc(
    const __nv_bfloat16* __restrict__ A, const __nv_bfloat16* __restrict__ Bw,
    const float* __restrict__ bias, float* __restrict__ C, int ldc)
{
    __shared__ __align__(128) uint8_t smA[2][8192];
    __shared__ __align__(128) uint8_t smB[2][8192];

    const int tid = threadIdx.x;
    const int lane = tid & 31;
    const int w = tid >> 5;
    const int wm = w & 1;        // 2 warps over M (64 rows each)
    const int wn = w >> 1;       // 4 warps over N (32 cols each)
    const int bm = blockIdx.y * 128;
    const int bn = blockIdx.x * 128;

    const __nv_bfloat16* Ab = A + (size_t)bm * K3;
    const __nv_bfloat16* Bb = Bw + (size_t)bn * K3;
    const uint32_t sAb = smem_to_u32(smA);
    const uint32_t sBb = smem_to_u32(smB);

    // ldmatrix per-thread offsets (relative to buffer base)
    const int lr = lane & 15;
    const int lch = lane >> 4;
    uint32_t offA[4][2], offB[2][2];
#pragma unroll
    for (int i = 0; i < 4; i++)
#pragma unroll
        for (int s = 0; s < 2; s++)
            offA[i][s] = swz(wm * 64 + i * 16 + lr, 2 * s + lch);
#pragma unroll
    for (int j2 = 0; j2 < 2; j2++)
#pragma unroll
        for (int s = 0; s < 2; s++)
            offB[j2][s] = swz(wn * 32 + j2 * 16 + lr, 2 * s + lch);

    float acc[4][4][4];
#pragma unroll
    for (int i = 0; i < 4; i++)
#pragma unroll
        for (int j = 0; j < 4; j++)
#pragma unroll
            for (int r = 0; r < 4; r++) acc[i][j][r] = 0.0f;

    // prologue
    gemm_issue_loads(Ab, Bb, sAb, sBb, tid, 0);
    CP_COMMIT();

    for (int kc = 0; kc < KCH32; kc++) {
        const int buf = kc & 1;
        if (kc + 1 < KCH32) {
            gemm_issue_loads(Ab, Bb, sAb + (buf ^ 1) * 8192, sBb + (buf ^ 1) * 8192, tid, kc + 1);
            CP_COMMIT();
            CP_WAIT1();
        } else {
            CP_WAIT0();
        }
        __syncthreads();

        const uint32_t sA = sAb + buf * 8192;
        const uint32_t sB = sBb + buf * 8192;
#pragma unroll
        for (int s = 0; s < 2; s++) {
            uint32_t a[4][4];
#pragma unroll
            for (int i = 0; i < 4; i++)
                LDSM_X4(a[i][0], a[i][1], a[i][2], a[i][3], sA + offA[i][s]);
            uint32_t b[4][2];
#pragma unroll
            for (int j2 = 0; j2 < 2; j2++) {
                uint32_t r0, r1, r2, r3;
                LDSM_X4(r0, r1, r2, r3, sB + offB[j2][s]);
                b[2 * j2][0] = r0; b[2 * j2][1] = r2;
                b[2 * j2 + 1][0] = r1; b[2 * j2 + 1][1] = r3;
            }
#pragma unroll
            for (int i = 0; i < 4; i++)
#pragma unroll
                for (int j = 0; j < 4; j++)
                    MMA16816(acc[i][j], a[i], b[j]);
        }
        __syncthreads();   // protect buf from being overwritten by next issue
    }

    // epilogue: acc regs {c0,c1}=row g, cols c,c+1 ; {c2,c3}=row g+8
#pragma unroll
    for (int i = 0; i < 4; i++) {
        const int r0 = bm + wm * 64 + i * 16 + (lane >> 2);
#pragma unroll
        for (int half = 0; half < 2; half++) {
            const int row = r0 + half * 8;
            if (row < MTOT) {
                float* crow = C + (size_t)row * ldc + bn + wn * 32;
                const float* brow = bias + bn + wn * 32;
#pragma unroll
                for (int j = 0; j < 4; j++) {
                    const int col = j * 8 + ((lane & 3) << 1);
                    float2 o;
                    o.x = acc[i][j][half * 2 + 0] + brow[col];
                    o.y = acc[i][j][half * 2 + 1] + brow[col + 1];
                    *(float2*)(crow + col) = o;
                }
            }
        }
    }
}

// ---------------------------------------------------------------------------
// RoPE in-place on Q,K slices of g_qkv (tokens 1..196), interleaved pairs.
// ---------------------------------------------------------------------------
__global__ void rope_kernel() {
    const int PAIRS = BB * HH * SEQ * (DD / 2);
    int idx = blockIdx.x * blockDim.x + threadIdx.x;
    if (idx >= 2 * PAIRS) return;
    int which = (idx < PAIRS) ? 0 : 1;
    int p = which ? (idx - PAIRS) : idx;
    int pr = p & 31;
    int rest = p >> 5;
    int t = rest % SEQ;
    int bh = rest / SEQ;
    int b = bh >> 4, h = bh & 15;
    int n = t + 1;
    size_t off = (size_t)(b * NN + n) * (3 * CC) + which * CC + h * DD + 2 * pr;

    float base0 = powf(10000.0f, -(float)(2 * ((2 * pr) & 31)) / 64.0f);
    float base1 = powf(10000.0f, -(float)(2 * ((2 * pr + 1) & 31)) / 64.0f);
    float a0 = (float)t * base0;
    float a1 = (float)t * base1;
    float c0, s0, c1, s1;
    sincosf(a0, &s0, &c0);
    sincosf(a1, &s1, &c1);

    float x0 = g_qkv[off], x1 = g_qkv[off + 1];
    g_qkv[off]     = x0 * c0 - x1 * s0;
    g_qkv[off + 1] = x1 * c1 + x0 * s1;
}

// ---------------------------------------------------------------------------
// Attention: one block per (b,h). K/V staged in smem, one thread per query
// row, online softmax, fp32 accumulation.
// ---------------------------------------------------------------------------
#define ATTN_THREADS 224
#define ATTN_SMEM (2 * NN * DD * (int)sizeof(float))   // 100864 B

__global__ __launch_bounds__(ATTN_THREADS) void attn_kernel()
{
    extern __shared__ float sm[];
    float* Ks = sm;
    float* Vs = sm + NN * DD;
    const int bh = blockIdx.x;
    const int b = bh >> 4, h = bh & 15;
    const int tid = threadIdx.x;
    const size_t rowbase = (size_t)b * NN * (3 * CC) + (size_t)h * DD;

    for (int i = tid; i < NN * (DD / 4); i += ATTN_THREADS) {
        int j = i >> 4;
        int d4 = (i & 15) << 2;
        size_t g = rowbase + (size_t)j * (3 * CC) + d4;
        *(float4*)(Ks + j * DD + d4) = *(const float4*)(g_qkv + g + CC);
        *(float4*)(Vs + j * DD + d4) = *(const float4*)(g_qkv + g + 2 * CC);
    }
    __syncthreads();
    if (tid >= NN) return;

    float q[DD];
    {
        const float4* qp = (const float4*)(g_qkv + rowbase + (size_t)tid * (3 * CC));
#pragma unroll
        for (int i = 0; i < 16; i++) {
            float4 v = qp[i];
            q[4 * i] = v.x; q[4 * i + 1] = v.y; q[4 * i + 2] = v.z; q[4 * i + 3] = v.w;
        }
    }

    float mx = -3.4e38f, l = 0.0f;
    float acc[DD];
#pragma unroll
    for (int d = 0; d < DD; d++) acc[d] = 0.0f;
    const float scale = 0.125f;

    for (int j = 0; j < NN; j++) {
        const float4* kr = (const float4*)(Ks + j * DD);
        float s = 0.0f;
#pragma unroll
        for (int i = 0; i < 16; i++) {
            float4 kv = kr[i];
            s = fmaf(q[4 * i], kv.x, s);
            s = fmaf(q[4 * i + 1], kv.y, s);
            s = fmaf(q[4 * i + 2], kv.z, s);
            s = fmaf(q[4 * i + 3], kv.w, s);
        }
        s *= scale;
        if (s > mx) {
            float corr = __expf(mx - s);
            l *= corr;
#pragma unroll
            for (int d = 0; d < DD; d++) acc[d] *= corr;
            mx = s;
        }
        float p = __expf(s - mx);
        l += p;
        const float4* vr = (const float4*)(Vs + j * DD);
#pragma unroll
        for (int i = 0; i < 16; i++) {
            float4 vv = vr[i];
            acc[4 * i]     = fmaf(p, vv.x, acc[4 * i]);
            acc[4 * i + 1] = fmaf(p, vv.y, acc[4 * i + 1]);
            acc[4 * i + 2] = fmaf(p, vv.z, acc[4 * i + 2]);
            acc[4 * i + 3] = fmaf(p, vv.w, acc[4 * i + 3]);
        }
    }

    float inv = 1.0f / l;
    float* op = g_att + (size_t)(b * NN + tid) * CC + h * DD;
#pragma unroll
    for (int i = 0; i < 16; i++) {
        float4 o;
        o.x = acc[4 * i] * inv;
        o.y = acc[4 * i + 1] * inv;
        o.z = acc[4 * i + 2] * inv;
        o.w = acc[4 * i + 3] * inv;
        *(float4*)(op + 4 * i) = o;
    }
}

// ---------------------------------------------------------------------------
// Launch
// ---------------------------------------------------------------------------
extern "C" void kernel_launch(void* const* d_in, const int* in_sizes, int n_in,
                              void* d_out, int out_size)
{
    const float* x      = (const float*)d_in[0];
    const float* qkv_w  = (const float*)d_in[1];
    const float* qkv_b  = (const float*)d_in[2];
    const float* proj_w = (const float*)d_in[3];
    const float* proj_b = (const float*)d_in[4];
    float* out = (float*)d_out;

    float *qkv = nullptr, *att = nullptr;
    __nv_bfloat16 *a1 = nullptr, *a2 = nullptr, *bq = nullptr, *bp = nullptr;
    cudaGetSymbolAddress((void**)&qkv, g_qkv);
    cudaGetSymbolAddress((void**)&att, g_att);
    cudaGetSymbolAddress((void**)&a1, g_A1);
    cudaGetSymbolAddress((void**)&a2, g_A2);
    cudaGetSymbolAddress((void**)&bq, g_Bq);
    cudaGetSymbolAddress((void**)&bp, g_Bp);

    cudaFuncSetAttribute(attn_kernel, cudaFuncAttributeMaxDynamicSharedMemorySize, ATTN_SMEM);

    // 1) split weights + input to bf16 hi/lo, K-expanded
    split_bf16_kernel<<<(3 * CC * 256 + 255) / 256, 256>>>(qkv_w, bq, 3 * CC, 0);
    split_bf16_kernel<<<(CC * 256 + 255) / 256, 256>>>(proj_w, bp, CC, 0);
    split_bf16_kernel<<<(MTOT * 256 + 255) / 256, 256>>>(x, a1, MTOT, 1);

    // 2) QKV GEMM (tensor cores): (12608,3072) = A1' @ Bq'^T + qkv_b
    {
        dim3 grid(3 * CC / 128, MPAD / 128);
        gemm_tc<<<grid, 256>>>(a1, bq, qkv_b, qkv, 3 * CC);
    }

    // 3) RoPE on Q,K (in place)
    {
        const int PAIRS = BB * HH * SEQ * (DD / 2);
        rope_kernel<<<(2 * PAIRS + 255) / 256, 256>>>();
    }

    // 4) Attention
    attn_kernel<<<BB * HH, ATTN_THREADS, ATTN_SMEM>>>();

    // 5) split attention output, then proj GEMM (tensor cores)
    split_bf16_kernel<<<(MTOT * 256 + 255) / 256, 256>>>(att, a2, MTOT, 1);
    {
        dim3 grid(CC / 128, MPAD / 128);
        gemm_tc<<<grid, 256>>>(a2, bp, proj_b, out, CC);
    }
}